// round 9
// baseline (speedup 1.0000x reference)
#include <cuda_runtime.h>
#include <cuda_bf16.h>
#include <stdint.h>
#include <math.h>

#define T_TOK 1024
#define H_DIM 2048
#define I_DIM 1408
#define E_NUM 8

#define NSTG 3
#define STG_B 32768
#define SMEM_TOT (NSTG * STG_B)   // 96 KB -> 2 CTAs/SM

#define EGW_N (E_NUM * I_DIM * H_DIM)
#define SGW_N (I_DIM * H_DIM)
#define X_N   (T_TOK * H_DIM)
#define H_ROWS ((E_NUM + 1) * T_TOK)

// ---------------- device scratch ----------------
__device__ int   g_count[E_NUM];
__device__ int   g_tok[E_NUM * T_TOK];
__device__ float g_wt [E_NUM * T_TOK];

__device__ __align__(16) __nv_bfloat16 cx_hi[X_N],  cx_lo[X_N];
__device__ __align__(16) __nv_bfloat16 cgw_hi[EGW_N], cgw_lo[EGW_N];
__device__ __align__(16) __nv_bfloat16 cuw_hi[EGW_N], cuw_lo[EGW_N];
__device__ __align__(16) __nv_bfloat16 cdw_hi[EGW_N], cdw_lo[EGW_N];
__device__ __align__(16) __nv_bfloat16 csg_hi[SGW_N], csg_lo[SGW_N];
__device__ __align__(16) __nv_bfloat16 csu_hi[SGW_N], csu_lo[SGW_N];
__device__ __align__(16) __nv_bfloat16 csd_hi[SGW_N], csd_lo[SGW_N];
__device__ __align__(16) __nv_bfloat16 h_hi[(size_t)H_ROWS * I_DIM];
__device__ __align__(16) __nv_bfloat16 h_lo[(size_t)H_ROWS * I_DIM];

// ---------------- PTX helpers ----------------
__device__ __forceinline__ uint32_t smem_u32(const void* p) {
    uint32_t a;
    asm("{ .reg .u64 t; cvta.to.shared.u64 t, %1; cvt.u32.u64 %0, t; }" : "=r"(a) : "l"(p));
    return a;
}
__device__ __forceinline__ void cpa(uint32_t dst, const void* src) {
    asm volatile("cp.async.cg.shared.global [%0], [%1], 16;" :: "r"(dst), "l"(src));
}
#define CPA_COMMIT() asm volatile("cp.async.commit_group;" ::: "memory")
#define CPA_WAIT1()  asm volatile("cp.async.wait_group 1;" ::: "memory")

__device__ __forceinline__ void ldmx4(uint32_t* r, uint32_t a) {
    asm volatile("ldmatrix.sync.aligned.m8n8.x4.shared.b16 {%0,%1,%2,%3}, [%4];"
        : "=r"(r[0]), "=r"(r[1]), "=r"(r[2]), "=r"(r[3]) : "r"(a));
}
__device__ __forceinline__ void mma16816(float* c, const uint32_t* a, uint32_t b0, uint32_t b1) {
    asm volatile("mma.sync.aligned.m16n8k16.row.col.f32.bf16.bf16.f32 "
        "{%0,%1,%2,%3},{%4,%5,%6,%7},{%8,%9},{%0,%1,%2,%3};"
        : "+f"(c[0]), "+f"(c[1]), "+f"(c[2]), "+f"(c[3])
        : "r"(a[0]), "r"(a[1]), "r"(a[2]), "r"(a[3]), "r"(b0), "r"(b1));
}

// ---------------- small kernels ----------------
__global__ void zero_kernel(float* __restrict__ out, int n) {
    int i = blockIdx.x * blockDim.x + threadIdx.x;
    if (i < n) out[i] = 0.0f;
    if (i < E_NUM) g_count[i] = 0;
}

__global__ void routing_kernel(const float* __restrict__ x, const float* __restrict__ gw) {
    int t = blockIdx.x * blockDim.x + threadIdx.x;
    if (t >= T_TOK) return;
    float logits[E_NUM];
#pragma unroll
    for (int e = 0; e < E_NUM; e++) logits[e] = 0.0f;
    const float* xr = x + (size_t)t * H_DIM;
    for (int h = 0; h < H_DIM; h += 4) {
        float4 xv = *(const float4*)(xr + h);
#pragma unroll
        for (int e = 0; e < E_NUM; e++) {
            const float* wr = gw + (size_t)e * H_DIM + h;
            logits[e] += xv.x * wr[0] + xv.y * wr[1] + xv.z * wr[2] + xv.w * wr[3];
        }
    }
    int i0 = 0;
#pragma unroll
    for (int e = 1; e < E_NUM; e++) if (logits[e] > logits[i0]) i0 = e;
    int i1 = -1;
#pragma unroll
    for (int e = 0; e < E_NUM; e++) {
        if (e == i0) continue;
        if (i1 < 0 || logits[e] > logits[i1]) i1 = e;
    }
    float e1 = expf(logits[i1] - logits[i0]);
    float inv = 1.0f / (1.0f + e1);
    int s0 = atomicAdd(&g_count[i0], 1);
    g_tok[i0 * T_TOK + s0] = t;  g_wt[i0 * T_TOK + s0] = inv;
    int s1 = atomicAdd(&g_count[i1], 1);
    g_tok[i1 * T_TOK + s1] = t;  g_wt[i1 * T_TOK + s1] = e1 * inv;
}

__device__ __forceinline__ uint32_t b2u(__nv_bfloat162 h) { return *reinterpret_cast<uint32_t*>(&h); }

__global__ void cvt_kernel(const float* __restrict__ src, __nv_bfloat16* __restrict__ hi,
                           __nv_bfloat16* __restrict__ lo, int n4) {
    int i = blockIdx.x * blockDim.x + threadIdx.x;
    if (i >= n4) return;
    float4 v = *((const float4*)src + i);
    __nv_bfloat162 h0 = __floats2bfloat162_rn(v.x, v.y);
    __nv_bfloat162 h1 = __floats2bfloat162_rn(v.z, v.w);
    __nv_bfloat162 l0 = __floats2bfloat162_rn(v.x - __low2float(h0), v.y - __high2float(h0));
    __nv_bfloat162 l1 = __floats2bfloat162_rn(v.z - __low2float(h1), v.w - __high2float(h1));
    *((uint2*)hi + i) = make_uint2(b2u(h0), b2u(h1));
    *((uint2*)lo + i) = make_uint2(b2u(l0), b2u(l1));
}

// ============================================================================
// gate+up GEMM: BM=128, BN=64 per matrix (gate & up), BK=32, 256 thr = 8 warps
// (2m x 4n), warp tile 64x16 per matrix. Rows pack [hi 64B | lo 64B] (128B).
// smem/stage: A 16K | Bgate 8K | Bup 8K = 32KB
// ============================================================================
__global__ void __launch_bounds__(256, 2) gu_kernel(int zbase) {
    extern __shared__ __align__(1024) char sm[];
    const int z = blockIdx.z + zbase;
    const int count = (z < E_NUM) ? g_count[z] : T_TOK;
    const int m0 = blockIdx.y * 128;
    if (m0 >= count) return;
    const int n0 = blockIdx.x * 64;

    const int tid = threadIdx.x, lane = tid & 31, wid = tid >> 5;
    const int wm = wid & 1, wn = wid >> 1;
    const uint32_t sb = smem_u32(sm);

    // ---- loader: A — 128 rows, 2 thr/row, each 2 hi + 2 lo units ----
    const int lr = tid >> 1, lh = tid & 1;
    const int mrow = m0 + lr;
    int tok = (z < E_NUM) ? ((mrow < count) ? g_tok[z * T_TOK + mrow] : 0) : mrow;
    const char* srcAh = (const char*)(cx_hi + (size_t)tok * H_DIM);
    const char* srcAl = (const char*)(cx_lo + (size_t)tok * H_DIM);
    const uint32_t SA = (uint32_t)(lr & 7) << 4;
    const uint32_t rowA = (uint32_t)(lr * 128);
    // ---- loader: B — mat (gate/up), 64 rows, 2 thr/row ----
    const int matB = tid >> 7, rowb = (tid & 127) >> 1, bh2 = tid & 1;
    const __nv_bfloat16 *wbh, *wbl;
    if (z < E_NUM) {
        size_t eo = (size_t)z * I_DIM * H_DIM;
        wbh = matB ? cuw_hi + eo : cgw_hi + eo;
        wbl = matB ? cuw_lo + eo : cgw_lo + eo;
    } else {
        wbh = matB ? csu_hi : csg_hi;
        wbl = matB ? csu_lo : csg_lo;
    }
    const char* srcBh = (const char*)(wbh + (size_t)(n0 + rowb) * H_DIM);
    const char* srcBl = (const char*)(wbl + (size_t)(n0 + rowb) * H_DIM);
    const uint32_t SB = (uint32_t)(rowb & 7) << 4;
    const uint32_t rowBoff = 16384u + (uint32_t)matB * 8192u + (uint32_t)(rowb * 128);

    auto load_stage = [&](int chunk, int stg) {
        uint32_t base = sb + stg * STG_B;
        int koff = chunk * 64;   // 32 elems * 2B
#pragma unroll
        for (int uu = 0; uu < 2; uu++) {
            uint32_t u = (uint32_t)(lh * 2 + uu);
            cpa(base + rowA + ((u << 4) ^ SA),        srcAh + koff + u * 16);
            cpa(base + rowA + (((u + 4) << 4) ^ SA),  srcAl + koff + u * 16);
        }
#pragma unroll
        for (int uu = 0; uu < 2; uu++) {
            uint32_t u = (uint32_t)(bh2 * 2 + uu);
            cpa(base + rowBoff + ((u << 4) ^ SB),       srcBh + koff + u * 16);
            cpa(base + rowBoff + (((u + 4) << 4) ^ SB), srcBl + koff + u * 16);
        }
    };

    const int ra = wm * 64 + (((lane >> 3) & 1) << 3) + (lane & 7);
    const uint32_t Sa = (uint32_t)(ra & 7) << 4;
    const int rbn = wn * 16 + (((lane >> 3) & 1) << 3) + (lane & 7);
    const uint32_t Sbn = (uint32_t)(rbn & 7) << 4;
    const uint32_t g2 = (uint32_t)(lane >> 4) << 4;

    float acc[2][4][2][4];   // [mat][mf][nf][4]
#pragma unroll
    for (int a = 0; a < 2; a++)
#pragma unroll
        for (int b = 0; b < 4; b++)
#pragma unroll
            for (int c = 0; c < 2; c++)
#pragma unroll
                for (int d = 0; d < 4; d++) acc[a][b][c][d] = 0.0f;

    load_stage(0, 0); CPA_COMMIT();
    load_stage(1, 1); CPA_COMMIT();

    const int NC = H_DIM / 32;  // 64
    for (int c = 0; c < NC; c++) {
        CPA_WAIT1();
        __syncthreads();
        if (c + 2 < NC) load_stage(c + 2, (c + 2) % NSTG);
        CPA_COMMIT();
        uint32_t base = sb + (c % NSTG) * STG_B;
#pragma unroll
        for (int ks = 0; ks < 2; ks++) {
            uint32_t kx = ((uint32_t)ks << 5) | g2;
            uint32_t Ah[4][4], Al[4][4];
#pragma unroll
            for (int mf = 0; mf < 4; mf++) {
                uint32_t ro = base + (uint32_t)((ra + mf * 16) * 128);
                ldmx4(Ah[mf], ro + (kx ^ Sa));
                ldmx4(Al[mf], ro + ((kx + 64) ^ Sa));
            }
#pragma unroll
            for (int mat = 0; mat < 2; mat++) {
                uint32_t bh[4], bl[4];
                uint32_t bo = base + 16384u + (uint32_t)mat * 8192u + (uint32_t)(rbn * 128);
                ldmx4(bh, bo + (kx ^ Sbn));
                ldmx4(bl, bo + ((kx + 64) ^ Sbn));
#pragma unroll
                for (int mf = 0; mf < 4; mf++) {
#pragma unroll
                    for (int nf = 0; nf < 2; nf++) {
                        mma16816(acc[mat][mf][nf], Ah[mf], bh[nf], bh[nf + 2]);
                        mma16816(acc[mat][mf][nf], Ah[mf], bl[nf], bl[nf + 2]);
                        mma16816(acc[mat][mf][nf], Al[mf], bh[nf], bh[nf + 2]);
                    }
                }
            }
        }
    }

    // ---- epilogue: silu(g)*u -> h hi/lo ----
    const size_t rowbase = (z < E_NUM) ? (size_t)z * T_TOK : (size_t)E_NUM * T_TOK;
#pragma unroll
    for (int mf = 0; mf < 4; mf++) {
        int R0 = m0 + wm * 64 + mf * 16 + (lane >> 2);
#pragma unroll
        for (int nf = 0; nf < 2; nf++) {
            int C = n0 + wn * 16 + nf * 8 + (lane & 3) * 2;
            float* gf = acc[0][mf][nf];
            float* uf = acc[1][mf][nf];
#pragma unroll
            for (int hr = 0; hr < 2; hr++) {
                int R = R0 + hr * 8;
                if (R < count) {
                    float ga = gf[hr * 2], gb = gf[hr * 2 + 1];
                    float ua = uf[hr * 2], ub = uf[hr * 2 + 1];
                    float ha = ga / (1.0f + __expf(-ga)) * ua;
                    float hb = gb / (1.0f + __expf(-gb)) * ub;
                    __nv_bfloat162 hi = __floats2bfloat162_rn(ha, hb);
                    __nv_bfloat162 lo = __floats2bfloat162_rn(ha - __low2float(hi), hb - __high2float(hi));
                    size_t off = (rowbase + R) * (size_t)I_DIM + C;
                    *(__nv_bfloat162*)(h_hi + off) = hi;
                    *(__nv_bfloat162*)(h_lo + off) = lo;
                }
            }
        }
    }
}

// ============================================================================
// down GEMM: BM=128, BN=128, BK=32, 256 thr = 8 warps (2m x 4n), warp 64x32
// smem/stage: A 16K | B 16K = 32KB
// ============================================================================
__global__ void __launch_bounds__(256, 2) dn_kernel(float* __restrict__ out) {
    extern __shared__ __align__(1024) char sm[];
    const int z = blockIdx.z;
    const int count = (z < E_NUM) ? g_count[z] : T_TOK;
    const int m0 = blockIdx.y * 128;
    if (m0 >= count) return;
    const int n0 = blockIdx.x * 128;

    const int tid = threadIdx.x, lane = tid & 31, wid = tid >> 5;
    const int wm = wid & 1, wn = wid >> 1;
    const uint32_t sb = smem_u32(sm);
    const size_t rowbase = (z < E_NUM) ? (size_t)z * T_TOK : (size_t)E_NUM * T_TOK;

    // ---- loaders ----
    const int lr = tid >> 1, lh = tid & 1;
    const char* srcAh = (const char*)(h_hi + (rowbase + m0 + lr) * (size_t)I_DIM);
    const char* srcAl = (const char*)(h_lo + (rowbase + m0 + lr) * (size_t)I_DIM);
    const uint32_t SA = (uint32_t)(lr & 7) << 4;
    const uint32_t rowA = (uint32_t)(lr * 128);

    const __nv_bfloat16 *wdh, *wdl;
    if (z < E_NUM) {
        size_t eo = (size_t)z * H_DIM * I_DIM;
        wdh = cdw_hi + eo;  wdl = cdw_lo + eo;
    } else {
        wdh = csd_hi;  wdl = csd_lo;
    }
    const char* srcBh = (const char*)(wdh + (size_t)(n0 + lr) * I_DIM);
    const char* srcBl = (const char*)(wdl + (size_t)(n0 + lr) * I_DIM);
    const uint32_t rowBoff = 16384u + rowA;

    auto load_stage = [&](int chunk, int stg) {
        uint32_t base = sb + stg * STG_B;
        int koff = chunk * 64;
#pragma unroll
        for (int uu = 0; uu < 2; uu++) {
            uint32_t u = (uint32_t)(lh * 2 + uu);
            cpa(base + rowA + ((u << 4) ^ SA),           srcAh + koff + u * 16);
            cpa(base + rowA + (((u + 4) << 4) ^ SA),     srcAl + koff + u * 16);
            cpa(base + rowBoff + ((u << 4) ^ SA),        srcBh + koff + u * 16);
            cpa(base + rowBoff + (((u + 4) << 4) ^ SA),  srcBl + koff + u * 16);
        }
    };

    const int ra = wm * 64 + (((lane >> 3) & 1) << 3) + (lane & 7);
    const uint32_t Sa = (uint32_t)(ra & 7) << 4;
    const int rb0 = wn * 32 + (((lane >> 3) & 1) << 3) + (lane & 7);
    const int rb1 = rb0 + 16;
    const uint32_t Sb0 = (uint32_t)(rb0 & 7) << 4;
    const uint32_t Sb1 = (uint32_t)(rb1 & 7) << 4;
    const uint32_t g2 = (uint32_t)(lane >> 4) << 4;

    float acc[4][4][4];   // [mf][nb*2+nf][4]
#pragma unroll
    for (int a = 0; a < 4; a++)
#pragma unroll
        for (int b = 0; b < 4; b++)
#pragma unroll
            for (int c = 0; c < 4; c++) acc[a][b][c] = 0.0f;

    load_stage(0, 0); CPA_COMMIT();
    load_stage(1, 1); CPA_COMMIT();

    const int NC = I_DIM / 32;  // 44
    for (int c = 0; c < NC; c++) {
        CPA_WAIT1();
        __syncthreads();
        if (c + 2 < NC) load_stage(c + 2, (c + 2) % NSTG);
        CPA_COMMIT();
        uint32_t base = sb + (c % NSTG) * STG_B;
#pragma unroll
        for (int ks = 0; ks < 2; ks++) {
            uint32_t kx = ((uint32_t)ks << 5) | g2;
            uint32_t Ah[4][4], Al[4][4];
#pragma unroll
            for (int mf = 0; mf < 4; mf++) {
                uint32_t ro = base + (uint32_t)((ra + mf * 16) * 128);
                ldmx4(Ah[mf], ro + (kx ^ Sa));
                ldmx4(Al[mf], ro + ((kx + 64) ^ Sa));
            }
#pragma unroll
            for (int nb = 0; nb < 2; nb++) {
                uint32_t bh[4], bl[4];
                uint32_t bo = base + 16384u + (uint32_t)((nb ? rb1 : rb0) * 128);
                uint32_t Sx = nb ? Sb1 : Sb0;
                ldmx4(bh, bo + (kx ^ Sx));
                ldmx4(bl, bo + ((kx + 64) ^ Sx));
#pragma unroll
                for (int mf = 0; mf < 4; mf++) {
#pragma unroll
                    for (int nf = 0; nf < 2; nf++) {
                        mma16816(acc[mf][nb * 2 + nf], Ah[mf], bh[nf], bh[nf + 2]);
                        mma16816(acc[mf][nb * 2 + nf], Ah[mf], bl[nf], bl[nf + 2]);
                        mma16816(acc[mf][nb * 2 + nf], Al[mf], bh[nf], bh[nf + 2]);
                    }
                }
            }
        }
    }

    // ---- epilogue: weighted atomic scatter ----
#pragma unroll
    for (int mf = 0; mf < 4; mf++) {
        int R0 = m0 + wm * 64 + mf * 16 + (lane >> 2);
#pragma unroll
        for (int hr = 0; hr < 2; hr++) {
            int R = R0 + hr * 8;
            if (R < count) {
                int t; float wt;
                if (z < E_NUM) { t = g_tok[z * T_TOK + R]; wt = g_wt[z * T_TOK + R]; }
                else           { t = R; wt = 1.0f; }
                float* orow = out + (size_t)t * H_DIM;
#pragma unroll
                for (int q = 0; q < 4; q++) {
                    int C = n0 + wn * 32 + q * 8 + (lane & 3) * 2;
                    atomicAdd(&orow[C],     wt * acc[mf][q][hr * 2]);
                    atomicAdd(&orow[C + 1], wt * acc[mf][q][hr * 2 + 1]);
                }
            }
        }
    }
}

// ---------------- launch ----------------
extern "C" void kernel_launch(void* const* d_in, const int* in_sizes, int n_in,
                              void* d_out, int out_size) {
    const float* x   = (const float*)d_in[0];
    const float* gw  = (const float*)d_in[1];
    const float* egw = (const float*)d_in[2];
    const float* euw = (const float*)d_in[3];
    const float* edw = (const float*)d_in[4];
    const float* sgw = (const float*)d_in[5];
    const float* suw = (const float*)d_in[6];
    const float* sdw = (const float*)d_in[7];
    float* out = (float*)d_out;

    cudaFuncSetAttribute(gu_kernel, cudaFuncAttributeMaxDynamicSharedMemorySize, SMEM_TOT);
    cudaFuncSetAttribute(dn_kernel, cudaFuncAttributeMaxDynamicSharedMemorySize, SMEM_TOT);

    __nv_bfloat16 *p_cx_hi, *p_cx_lo, *p_cgw_hi, *p_cgw_lo, *p_cuw_hi, *p_cuw_lo;
    __nv_bfloat16 *p_cdw_hi, *p_cdw_lo, *p_csg_hi, *p_csg_lo, *p_csu_hi, *p_csu_lo, *p_csd_hi, *p_csd_lo;
    cudaGetSymbolAddress((void**)&p_cx_hi, cx_hi);   cudaGetSymbolAddress((void**)&p_cx_lo, cx_lo);
    cudaGetSymbolAddress((void**)&p_cgw_hi, cgw_hi); cudaGetSymbolAddress((void**)&p_cgw_lo, cgw_lo);
    cudaGetSymbolAddress((void**)&p_cuw_hi, cuw_hi); cudaGetSymbolAddress((void**)&p_cuw_lo, cuw_lo);
    cudaGetSymbolAddress((void**)&p_cdw_hi, cdw_hi); cudaGetSymbolAddress((void**)&p_cdw_lo, cdw_lo);
    cudaGetSymbolAddress((void**)&p_csg_hi, csg_hi); cudaGetSymbolAddress((void**)&p_csg_lo, csg_lo);
    cudaGetSymbolAddress((void**)&p_csu_hi, csu_hi); cudaGetSymbolAddress((void**)&p_csu_lo, csu_lo);
    cudaGetSymbolAddress((void**)&p_csd_hi, csd_hi); cudaGetSymbolAddress((void**)&p_csd_lo, csd_lo);

    int n_out = T_TOK * H_DIM;
    // Launch order puts routed gu_kernel at launch #6 so ncu (-s 5 -c 1) profiles it.
    zero_kernel<<<(n_out + 255) / 256, 256>>>(out, n_out);                       // 1
    routing_kernel<<<T_TOK / 256, 256>>>(x, gw);                                 // 2
    cvt_kernel<<<(X_N / 4 + 255) / 256, 256>>>(x, p_cx_hi, p_cx_lo, X_N / 4);    // 3
    cvt_kernel<<<(EGW_N / 4 + 255) / 256, 256>>>(egw, p_cgw_hi, p_cgw_lo, EGW_N / 4); // 4
    cvt_kernel<<<(EGW_N / 4 + 255) / 256, 256>>>(euw, p_cuw_hi, p_cuw_lo, EGW_N / 4); // 5
    gu_kernel<<<dim3(I_DIM / 64, T_TOK / 128, E_NUM), 256, SMEM_TOT>>>(0);       // 6 <- profiled
    cvt_kernel<<<(EGW_N / 4 + 255) / 256, 256>>>(edw, p_cdw_hi, p_cdw_lo, EGW_N / 4); // 7
    cvt_kernel<<<(SGW_N / 4 + 255) / 256, 256>>>(sgw, p_csg_hi, p_csg_lo, SGW_N / 4); // 8
    cvt_kernel<<<(SGW_N / 4 + 255) / 256, 256>>>(suw, p_csu_hi, p_csu_lo, SGW_N / 4); // 9
    cvt_kernel<<<(SGW_N / 4 + 255) / 256, 256>>>(sdw, p_csd_hi, p_csd_lo, SGW_N / 4); // 10
    gu_kernel<<<dim3(I_DIM / 64, T_TOK / 128, 1), 256, SMEM_TOT>>>(E_NUM);       // 11 (shared expert)
    dn_kernel<<<dim3(H_DIM / 128, T_TOK / 128, E_NUM + 1), 256, SMEM_TOT>>>(out);// 12
}

// round 10
// speedup vs baseline: 1.3174x; 1.3174x over previous
#include <cuda_runtime.h>
#include <cuda_fp16.h>
#include <stdint.h>
#include <math.h>

#define T_TOK 1024
#define H_DIM 2048
#define I_DIM 1408
#define E_NUM 8

#define NSTG 3
#define STG_B 49152
#define SMEM_TOT (NSTG * STG_B)   // 144 KB

#define EGW_N (E_NUM * I_DIM * H_DIM)
#define SGW_N (I_DIM * H_DIM)
#define X_N   (T_TOK * H_DIM)
#define H_ROWS ((E_NUM + 1) * T_TOK)

// ---------------- device scratch ----------------
__device__ int   g_count[E_NUM];
__device__ int   g_tok[E_NUM * T_TOK];
__device__ float g_wt [E_NUM * T_TOK];

__device__ __align__(16) __half cx_hi[X_N], cx_lo[X_N];
__device__ __align__(16) __half cgw[EGW_N];   // expert gate  (fp16 hi only)
__device__ __align__(16) __half cuw[EGW_N];   // expert up
__device__ __align__(16) __half cdw[EGW_N];   // expert down
__device__ __align__(16) __half csg[SGW_N], csu[SGW_N], csd[SGW_N];
__device__ __align__(16) __half h_hi[(size_t)H_ROWS * I_DIM];
__device__ __align__(16) __half h_lo[(size_t)H_ROWS * I_DIM];

// ---------------- PTX helpers ----------------
__device__ __forceinline__ uint32_t smem_u32(const void* p) {
    uint32_t a;
    asm("{ .reg .u64 t; cvta.to.shared.u64 t, %1; cvt.u32.u64 %0, t; }" : "=r"(a) : "l"(p));
    return a;
}
__device__ __forceinline__ void cpa(uint32_t dst, const void* src) {
    asm volatile("cp.async.cg.shared.global [%0], [%1], 16;" :: "r"(dst), "l"(src));
}
#define CPA_COMMIT() asm volatile("cp.async.commit_group;" ::: "memory")
#define CPA_WAIT1()  asm volatile("cp.async.wait_group 1;" ::: "memory")

__device__ __forceinline__ void ldmx4(uint32_t* r, uint32_t a) {
    asm volatile("ldmatrix.sync.aligned.m8n8.x4.shared.b16 {%0,%1,%2,%3}, [%4];"
        : "=r"(r[0]), "=r"(r[1]), "=r"(r[2]), "=r"(r[3]) : "r"(a));
}
__device__ __forceinline__ void mma16816(float* c, const uint32_t* a, uint32_t b0, uint32_t b1) {
    asm volatile("mma.sync.aligned.m16n8k16.row.col.f32.f16.f16.f32 "
        "{%0,%1,%2,%3},{%4,%5,%6,%7},{%8,%9},{%0,%1,%2,%3};"
        : "+f"(c[0]), "+f"(c[1]), "+f"(c[2]), "+f"(c[3])
        : "r"(a[0]), "r"(a[1]), "r"(a[2]), "r"(a[3]), "r"(b0), "r"(b1));
}
__device__ __forceinline__ uint32_t h2u(__half2 h) { return *reinterpret_cast<uint32_t*>(&h); }

// ---------------- small kernels ----------------
__global__ void zero_kernel(float* __restrict__ out, int n) {
    int i = blockIdx.x * blockDim.x + threadIdx.x;
    if (i < n) out[i] = 0.0f;
    if (i < E_NUM) g_count[i] = 0;
}

__global__ void routing_kernel(const float* __restrict__ x, const float* __restrict__ gw) {
    int t = blockIdx.x * blockDim.x + threadIdx.x;
    if (t >= T_TOK) return;
    float logits[E_NUM];
#pragma unroll
    for (int e = 0; e < E_NUM; e++) logits[e] = 0.0f;
    const float* xr = x + (size_t)t * H_DIM;
    for (int h = 0; h < H_DIM; h += 4) {
        float4 xv = *(const float4*)(xr + h);
#pragma unroll
        for (int e = 0; e < E_NUM; e++) {
            const float* wr = gw + (size_t)e * H_DIM + h;
            logits[e] += xv.x * wr[0] + xv.y * wr[1] + xv.z * wr[2] + xv.w * wr[3];
        }
    }
    int i0 = 0;
#pragma unroll
    for (int e = 1; e < E_NUM; e++) if (logits[e] > logits[i0]) i0 = e;
    int i1 = -1;
#pragma unroll
    for (int e = 0; e < E_NUM; e++) {
        if (e == i0) continue;
        if (i1 < 0 || logits[e] > logits[i1]) i1 = e;
    }
    float e1 = expf(logits[i1] - logits[i0]);
    float inv = 1.0f / (1.0f + e1);
    int s0 = atomicAdd(&g_count[i0], 1);
    g_tok[i0 * T_TOK + s0] = t;  g_wt[i0 * T_TOK + s0] = inv;
    int s1 = atomicAdd(&g_count[i1], 1);
    g_tok[i1 * T_TOK + s1] = t;  g_wt[i1 * T_TOK + s1] = e1 * inv;
}

// fp32 -> fp16 hi + lo (exact 2-term split of activations)
__global__ void cvt_hilo_kernel(const float* __restrict__ src, __half* __restrict__ hi,
                                __half* __restrict__ lo, int n4) {
    int i = blockIdx.x * blockDim.x + threadIdx.x;
    if (i >= n4) return;
    float4 v = *((const float4*)src + i);
    __half2 h0 = __floats2half2_rn(v.x, v.y);
    __half2 h1 = __floats2half2_rn(v.z, v.w);
    __half2 l0 = __floats2half2_rn(v.x - __low2float(h0), v.y - __high2float(h0));
    __half2 l1 = __floats2half2_rn(v.z - __low2float(h1), v.w - __high2float(h1));
    *((uint2*)hi + i) = make_uint2(h2u(h0), h2u(h1));
    *((uint2*)lo + i) = make_uint2(h2u(l0), h2u(l1));
}

// fp32 -> fp16 (weights: hi only)
__global__ void cvt_hi_kernel(const float* __restrict__ src, __half* __restrict__ hi, int n4) {
    int i = blockIdx.x * blockDim.x + threadIdx.x;
    if (i >= n4) return;
    float4 v = *((const float4*)src + i);
    __half2 h0 = __floats2half2_rn(v.x, v.y);
    __half2 h1 = __floats2half2_rn(v.z, v.w);
    *((uint2*)hi + i) = make_uint2(h2u(h0), h2u(h1));
}

// ============================================================================
// gate+up GEMM: BM=128, BN=64 per matrix (gate & up), BK=64, 512 thr = 16 warps
// (4m x 4n), warp tile 32x16 per matrix. y = (A_hi + A_lo) x W_hi  (2 MMAs/term)
// smem/stage: Ahi 16K | Alo 16K | Ghi 8K | Uhi 8K = 48KB
// ============================================================================
__global__ void __launch_bounds__(512, 1) gu_kernel(int zbase) {
    extern __shared__ __align__(1024) char sm[];
    const int z = blockIdx.z + zbase;
    const int count = (z < E_NUM) ? g_count[z] : T_TOK;
    const int m0 = blockIdx.y * 128;
    if (m0 >= count) return;
    const int n0 = blockIdx.x * 64;

    const int tid = threadIdx.x, lane = tid & 31, wid = tid >> 5;
    const int wm = wid & 3, wn = wid >> 2;
    const uint32_t sb = smem_u32(sm);

    // ---- loader: A — 128 rows, 4 thr/row, 2 units each (hi & lo) ----
    const int lr = tid >> 2, lj = (tid & 3) * 2;
    const int mrow = m0 + lr;
    int tok = (z < E_NUM) ? ((mrow < count) ? g_tok[z * T_TOK + mrow] : 0) : mrow;
    const char* srcAh = (const char*)(cx_hi + (size_t)tok * H_DIM);
    const char* srcAl = (const char*)(cx_lo + (size_t)tok * H_DIM);
    const uint32_t SA = (uint32_t)(lr & 7) << 4;
    const uint32_t rowA = (uint32_t)(lr * 128);
    uint32_t dA[2];
#pragma unroll
    for (int uu = 0; uu < 2; uu++)
        dA[uu] = rowA + ((((uint32_t)(lj + uu)) << 4) ^ SA);

    // ---- loader: B — 2 buffers (Ghi, Uhi), 64 rows, 4 thr/row, 2 units ----
    const int selB = tid >> 8, rowb = (tid & 255) >> 2, bj = (tid & 3) * 2;
    const __half* wbh;
    if (z < E_NUM) {
        size_t eo = (size_t)z * I_DIM * H_DIM;
        wbh = selB ? cuw + eo : cgw + eo;
    } else {
        wbh = selB ? csu : csg;
    }
    const char* srcB = (const char*)(wbh + (size_t)(n0 + rowb) * H_DIM);
    const uint32_t SB = (uint32_t)(rowb & 7) << 4;
    const uint32_t rowBoff = 32768u + (uint32_t)selB * 8192u + (uint32_t)(rowb * 128);

    auto load_stage = [&](int chunk, int stg) {
        uint32_t base = sb + stg * STG_B;
        int koff = chunk * 128;   // 64 fp16 * 2B
#pragma unroll
        for (int uu = 0; uu < 2; uu++) {
            int so = koff + (lj + uu) * 16;
            cpa(base + dA[uu],          srcAh + so);
            cpa(base + 16384 + dA[uu],  srcAl + so);
        }
#pragma unroll
        for (int uu = 0; uu < 2; uu++) {
            uint32_t u = (uint32_t)(bj + uu);
            cpa(base + rowBoff + ((u << 4) ^ SB), srcB + koff + u * 16);
        }
    };

    const int ra = wm * 32 + (((lane >> 3) & 1) << 3) + (lane & 7);
    const uint32_t Sa = (uint32_t)(ra & 7) << 4;
    const int rbn = wn * 16 + (((lane >> 3) & 1) << 3) + (lane & 7);
    const uint32_t Sbn = (uint32_t)(rbn & 7) << 4;
    const uint32_t g2 = (uint32_t)(lane >> 4) << 4;

    float acc[2][2][2][4];   // [mat][mf][nf][4]
#pragma unroll
    for (int a = 0; a < 2; a++)
#pragma unroll
        for (int b = 0; b < 2; b++)
#pragma unroll
            for (int c = 0; c < 2; c++)
#pragma unroll
                for (int d = 0; d < 4; d++) acc[a][b][c][d] = 0.0f;

    load_stage(0, 0); CPA_COMMIT();
    load_stage(1, 1); CPA_COMMIT();

    const int NC = H_DIM / 64;  // 32
    for (int c = 0; c < NC; c++) {
        CPA_WAIT1();
        __syncthreads();
        if (c + 2 < NC) load_stage(c + 2, (c + 2) % NSTG);
        CPA_COMMIT();
        uint32_t base = sb + (c % NSTG) * STG_B;
#pragma unroll
        for (int ks = 0; ks < 4; ks++) {
            uint32_t kx = ((uint32_t)ks << 5) | g2;
            uint32_t Ah[2][4], Al[2][4];
#pragma unroll
            for (int mf = 0; mf < 2; mf++) {
                uint32_t ro = (uint32_t)((ra + mf * 16) * 128);
                ldmx4(Ah[mf], base + ro + (kx ^ Sa));
                ldmx4(Al[mf], base + 16384 + ro + (kx ^ Sa));
            }
#pragma unroll
            for (int mat = 0; mat < 2; mat++) {
                uint32_t bh[4];
                uint32_t bo = base + 32768 + (uint32_t)mat * 8192 + (uint32_t)(rbn * 128);
                ldmx4(bh, bo + (kx ^ Sbn));
#pragma unroll
                for (int mf = 0; mf < 2; mf++) {
#pragma unroll
                    for (int nf = 0; nf < 2; nf++) {
                        mma16816(acc[mat][mf][nf], Ah[mf], bh[nf], bh[nf + 2]);
                        mma16816(acc[mat][mf][nf], Al[mf], bh[nf], bh[nf + 2]);
                    }
                }
            }
        }
    }

    // ---- epilogue: silu(g)*u -> h hi/lo (fp16 split) ----
    const size_t rowbase = (z < E_NUM) ? (size_t)z * T_TOK : (size_t)E_NUM * T_TOK;
#pragma unroll
    for (int mf = 0; mf < 2; mf++) {
        int R0 = m0 + wm * 32 + mf * 16 + (lane >> 2);
#pragma unroll
        for (int nf = 0; nf < 2; nf++) {
            int C = n0 + wn * 16 + nf * 8 + (lane & 3) * 2;
            float* gf = acc[0][mf][nf];
            float* uf = acc[1][mf][nf];
#pragma unroll
            for (int hr = 0; hr < 2; hr++) {
                int R = R0 + hr * 8;
                if (R < count) {
                    float ga = gf[hr * 2], gb = gf[hr * 2 + 1];
                    float ua = uf[hr * 2], ub = uf[hr * 2 + 1];
                    float ha = ga / (1.0f + __expf(-ga)) * ua;
                    float hb = gb / (1.0f + __expf(-gb)) * ub;
                    __half2 hi = __floats2half2_rn(ha, hb);
                    __half2 lo = __floats2half2_rn(ha - __low2float(hi), hb - __high2float(hi));
                    size_t off = (rowbase + R) * (size_t)I_DIM + C;
                    *(__half2*)(h_hi + off) = hi;
                    *(__half2*)(h_lo + off) = lo;
                }
            }
        }
    }
}

// ============================================================================
// down GEMM: BM=128, BN=128, BK=64, 512 thr = 16 warps (4m x 4n), warp 32x32
// smem/stage: Ahi 16K | Alo 16K | Bhi 16K = 48KB
// ============================================================================
__global__ void __launch_bounds__(512, 1) dn_kernel(float* __restrict__ out) {
    extern __shared__ __align__(1024) char sm[];
    const int z = blockIdx.z;
    const int count = (z < E_NUM) ? g_count[z] : T_TOK;
    const int m0 = blockIdx.y * 128;
    if (m0 >= count) return;
    const int n0 = blockIdx.x * 128;

    const int tid = threadIdx.x, lane = tid & 31, wid = tid >> 5;
    const int wm = wid & 3, wn = wid >> 2;
    const uint32_t sb = smem_u32(sm);
    const size_t rowbase = (z < E_NUM) ? (size_t)z * T_TOK : (size_t)E_NUM * T_TOK;

    // ---- loader: A (h rows) ----
    const int lr = tid >> 2, lj = (tid & 3) * 2;
    const char* srcAh = (const char*)(h_hi + (rowbase + m0 + lr) * (size_t)I_DIM);
    const char* srcAl = (const char*)(h_lo + (rowbase + m0 + lr) * (size_t)I_DIM);
    const uint32_t SA = (uint32_t)(lr & 7) << 4;
    const uint32_t rowA = (uint32_t)(lr * 128);
    uint32_t dA[2];
#pragma unroll
    for (int uu = 0; uu < 2; uu++)
        dA[uu] = rowA + ((((uint32_t)(lj + uu)) << 4) ^ SA);

    // ---- loader: B (down weights, hi only): 128 rows, 4 thr/row, 2 units ----
    const __half* wdh = (z < E_NUM) ? cdw + (size_t)z * H_DIM * I_DIM : csd;
    const char* srcB = (const char*)(wdh + (size_t)(n0 + lr) * I_DIM);
    const uint32_t rowBoff = 32768u + rowA;

    auto load_stage = [&](int chunk, int stg) {
        uint32_t base = sb + stg * STG_B;
        int koff = chunk * 128;
#pragma unroll
        for (int uu = 0; uu < 2; uu++) {
            int so = koff + (lj + uu) * 16;
            cpa(base + dA[uu],           srcAh + so);
            cpa(base + 16384 + dA[uu],   srcAl + so);
            cpa(base + 16384 + dA[uu] + 16384, srcB + so);
        }
    };

    const int ra = wm * 32 + (((lane >> 3) & 1) << 3) + (lane & 7);
    const uint32_t Sa = (uint32_t)(ra & 7) << 4;
    const int rb0 = wn * 32 + (((lane >> 3) & 1) << 3) + (lane & 7);
    const int rb1 = rb0 + 16;
    const uint32_t Sb0 = (uint32_t)(rb0 & 7) << 4;
    const uint32_t Sb1 = (uint32_t)(rb1 & 7) << 4;
    const uint32_t g2 = (uint32_t)(lane >> 4) << 4;

    float acc[2][4][4];   // [mf][nb*2+nf][4]
#pragma unroll
    for (int a = 0; a < 2; a++)
#pragma unroll
        for (int b = 0; b < 4; b++)
#pragma unroll
            for (int c = 0; c < 4; c++) acc[a][b][c] = 0.0f;

    load_stage(0, 0); CPA_COMMIT();
    load_stage(1, 1); CPA_COMMIT();

    const int NC = I_DIM / 64;  // 22
    for (int c = 0; c < NC; c++) {
        CPA_WAIT1();
        __syncthreads();
        if (c + 2 < NC) load_stage(c + 2, (c + 2) % NSTG);
        CPA_COMMIT();
        uint32_t base = sb + (c % NSTG) * STG_B;
#pragma unroll
        for (int ks = 0; ks < 4; ks++) {
            uint32_t kx = ((uint32_t)ks << 5) | g2;
            uint32_t Ah[2][4], Al[2][4];
#pragma unroll
            for (int mf = 0; mf < 2; mf++) {
                uint32_t ro = (uint32_t)((ra + mf * 16) * 128);
                ldmx4(Ah[mf], base + ro + (kx ^ Sa));
                ldmx4(Al[mf], base + 16384 + ro + (kx ^ Sa));
            }
#pragma unroll
            for (int nb = 0; nb < 2; nb++) {
                uint32_t bh[4];
                uint32_t ro = (uint32_t)((nb ? rb1 : rb0) * 128);
                uint32_t Sx = nb ? Sb1 : Sb0;
                ldmx4(bh, base + 32768 + ro + (kx ^ Sx));
#pragma unroll
                for (int mf = 0; mf < 2; mf++) {
#pragma unroll
                    for (int nf = 0; nf < 2; nf++) {
                        mma16816(acc[mf][nb * 2 + nf], Ah[mf], bh[nf], bh[nf + 2]);
                        mma16816(acc[mf][nb * 2 + nf], Al[mf], bh[nf], bh[nf + 2]);
                    }
                }
            }
        }
    }

    // ---- epilogue: weighted atomic scatter ----
#pragma unroll
    for (int mf = 0; mf < 2; mf++) {
        int R0 = m0 + wm * 32 + mf * 16 + (lane >> 2);
#pragma unroll
        for (int hr = 0; hr < 2; hr++) {
            int R = R0 + hr * 8;
            if (R < count) {
                int t; float wt;
                if (z < E_NUM) { t = g_tok[z * T_TOK + R]; wt = g_wt[z * T_TOK + R]; }
                else           { t = R; wt = 1.0f; }
                float* orow = out + (size_t)t * H_DIM;
#pragma unroll
                for (int q = 0; q < 4; q++) {
                    int C = n0 + wn * 32 + q * 8 + (lane & 3) * 2;
                    atomicAdd(&orow[C],     wt * acc[mf][q][hr * 2]);
                    atomicAdd(&orow[C + 1], wt * acc[mf][q][hr * 2 + 1]);
                }
            }
        }
    }
}

// ---------------- launch ----------------
extern "C" void kernel_launch(void* const* d_in, const int* in_sizes, int n_in,
                              void* d_out, int out_size) {
    const float* x   = (const float*)d_in[0];
    const float* gw  = (const float*)d_in[1];
    const float* egw = (const float*)d_in[2];
    const float* euw = (const float*)d_in[3];
    const float* edw = (const float*)d_in[4];
    const float* sgw = (const float*)d_in[5];
    const float* suw = (const float*)d_in[6];
    const float* sdw = (const float*)d_in[7];
    float* out = (float*)d_out;

    cudaFuncSetAttribute(gu_kernel, cudaFuncAttributeMaxDynamicSharedMemorySize, SMEM_TOT);
    cudaFuncSetAttribute(dn_kernel, cudaFuncAttributeMaxDynamicSharedMemorySize, SMEM_TOT);

    __half *p_cx_hi, *p_cx_lo, *p_cgw, *p_cuw, *p_cdw, *p_csg, *p_csu, *p_csd;
    cudaGetSymbolAddress((void**)&p_cx_hi, cx_hi);
    cudaGetSymbolAddress((void**)&p_cx_lo, cx_lo);
    cudaGetSymbolAddress((void**)&p_cgw, cgw);
    cudaGetSymbolAddress((void**)&p_cuw, cuw);
    cudaGetSymbolAddress((void**)&p_cdw, cdw);
    cudaGetSymbolAddress((void**)&p_csg, csg);
    cudaGetSymbolAddress((void**)&p_csu, csu);
    cudaGetSymbolAddress((void**)&p_csd, csd);

    int n_out = T_TOK * H_DIM;
    zero_kernel<<<(n_out + 255) / 256, 256>>>(out, n_out);                         // 1
    routing_kernel<<<T_TOK / 256, 256>>>(x, gw);                                   // 2
    cvt_hilo_kernel<<<(X_N / 4 + 255) / 256, 256>>>(x, p_cx_hi, p_cx_lo, X_N / 4); // 3
    cvt_hi_kernel<<<(EGW_N / 4 + 255) / 256, 256>>>(egw, p_cgw, EGW_N / 4);        // 4
    cvt_hi_kernel<<<(EGW_N / 4 + 255) / 256, 256>>>(euw, p_cuw, EGW_N / 4);        // 5
    gu_kernel<<<dim3(I_DIM / 64, T_TOK / 128, E_NUM), 512, SMEM_TOT>>>(0);         // 6 <- profiled
    cvt_hi_kernel<<<(EGW_N / 4 + 255) / 256, 256>>>(edw, p_cdw, EGW_N / 4);        // 7
    cvt_hi_kernel<<<(SGW_N / 4 + 255) / 256, 256>>>(sgw, p_csg, SGW_N / 4);        // 8
    cvt_hi_kernel<<<(SGW_N / 4 + 255) / 256, 256>>>(suw, p_csu, SGW_N / 4);        // 9
    cvt_hi_kernel<<<(SGW_N / 4 + 255) / 256, 256>>>(sdw, p_csd, SGW_N / 4);        // 10
    gu_kernel<<<dim3(I_DIM / 64, T_TOK / 128, 1), 512, SMEM_TOT>>>(E_NUM);         // 11 (shared)
    dn_kernel<<<dim3(H_DIM / 128, T_TOK / 128, E_NUM + 1), 512, SMEM_TOT>>>(out);  // 12
}

// round 11
// speedup vs baseline: 1.8198x; 1.3814x over previous
#include <cuda_runtime.h>
#include <cuda_fp16.h>
#include <stdint.h>
#include <math.h>

#define T_TOK 1024
#define H_DIM 2048
#define I_DIM 1408
#define E_NUM 8

#define NSTG 3
#define STG_B 32768
#define SMEM_TOT (NSTG * STG_B)   // 96 KB -> 2 CTAs/SM

#define EGW_N (E_NUM * I_DIM * H_DIM)
#define SGW_N (I_DIM * H_DIM)
#define X_N   (T_TOK * H_DIM)
#define H_ROWS ((E_NUM + 1) * T_TOK)

// ---------------- device scratch ----------------
__device__ int   g_count[E_NUM];
__device__ int   g_tok[E_NUM * T_TOK];
__device__ float g_wt [E_NUM * T_TOK];

__device__ __align__(16) __half cx[X_N];
__device__ __align__(16) __half cgw[EGW_N];
__device__ __align__(16) __half cuw[EGW_N];
__device__ __align__(16) __half cdw[EGW_N];
__device__ __align__(16) __half csg[SGW_N], csu[SGW_N], csd[SGW_N];
__device__ __align__(16) __half h_buf[(size_t)H_ROWS * I_DIM];

// ---------------- PTX helpers ----------------
__device__ __forceinline__ uint32_t smem_u32(const void* p) {
    uint32_t a;
    asm("{ .reg .u64 t; cvta.to.shared.u64 t, %1; cvt.u32.u64 %0, t; }" : "=r"(a) : "l"(p));
    return a;
}
__device__ __forceinline__ void cpa(uint32_t dst, const void* src) {
    asm volatile("cp.async.cg.shared.global [%0], [%1], 16;" :: "r"(dst), "l"(src));
}
#define CPA_COMMIT() asm volatile("cp.async.commit_group;" ::: "memory")
#define CPA_WAIT1()  asm volatile("cp.async.wait_group 1;" ::: "memory")

__device__ __forceinline__ void ldmx4(uint32_t* r, uint32_t a) {
    asm volatile("ldmatrix.sync.aligned.m8n8.x4.shared.b16 {%0,%1,%2,%3}, [%4];"
        : "=r"(r[0]), "=r"(r[1]), "=r"(r[2]), "=r"(r[3]) : "r"(a));
}
__device__ __forceinline__ void mma16816(float* c, const uint32_t* a, uint32_t b0, uint32_t b1) {
    asm volatile("mma.sync.aligned.m16n8k16.row.col.f32.f16.f16.f32 "
        "{%0,%1,%2,%3},{%4,%5,%6,%7},{%8,%9},{%0,%1,%2,%3};"
        : "+f"(c[0]), "+f"(c[1]), "+f"(c[2]), "+f"(c[3])
        : "r"(a[0]), "r"(a[1]), "r"(a[2]), "r"(a[3]), "r"(b0), "r"(b1));
}
__device__ __forceinline__ uint32_t h2u(__half2 h) { return *reinterpret_cast<uint32_t*>(&h); }

// ---------------- small kernels ----------------
__global__ void zero_kernel(float* __restrict__ out, int n) {
    int i = blockIdx.x * blockDim.x + threadIdx.x;
    if (i < n) out[i] = 0.0f;
    if (i < E_NUM) g_count[i] = 0;
}

__global__ void routing_kernel(const float* __restrict__ x, const float* __restrict__ gw) {
    int t = blockIdx.x * blockDim.x + threadIdx.x;
    if (t >= T_TOK) return;
    float logits[E_NUM];
#pragma unroll
    for (int e = 0; e < E_NUM; e++) logits[e] = 0.0f;
    const float* xr = x + (size_t)t * H_DIM;
    for (int h = 0; h < H_DIM; h += 4) {
        float4 xv = *(const float4*)(xr + h);
#pragma unroll
        for (int e = 0; e < E_NUM; e++) {
            const float* wr = gw + (size_t)e * H_DIM + h;
            logits[e] += xv.x * wr[0] + xv.y * wr[1] + xv.z * wr[2] + xv.w * wr[3];
        }
    }
    int i0 = 0;
#pragma unroll
    for (int e = 1; e < E_NUM; e++) if (logits[e] > logits[i0]) i0 = e;
    int i1 = -1;
#pragma unroll
    for (int e = 0; e < E_NUM; e++) {
        if (e == i0) continue;
        if (i1 < 0 || logits[e] > logits[i1]) i1 = e;
    }
    float e1 = expf(logits[i1] - logits[i0]);
    float inv = 1.0f / (1.0f + e1);
    int s0 = atomicAdd(&g_count[i0], 1);
    g_tok[i0 * T_TOK + s0] = t;  g_wt[i0 * T_TOK + s0] = inv;
    int s1 = atomicAdd(&g_count[i1], 1);
    g_tok[i1 * T_TOK + s1] = t;  g_wt[i1 * T_TOK + s1] = e1 * inv;
}

// fp32 -> fp16
__global__ void cvt_hi_kernel(const float* __restrict__ src, __half* __restrict__ hi, int n4) {
    int i = blockIdx.x * blockDim.x + threadIdx.x;
    if (i >= n4) return;
    float4 v = *((const float4*)src + i);
    __half2 h0 = __floats2half2_rn(v.x, v.y);
    __half2 h1 = __floats2half2_rn(v.z, v.w);
    *((uint2*)hi + i) = make_uint2(h2u(h0), h2u(h1));
}

// ============================================================================
// gate+up GEMM: BM=128, BN=64 per matrix (gate & up), BK=64, 512 thr = 16 warps
// (4m x 4n), warp tile 32x16 per matrix, pure fp16.
// smem/stage: A 16K | Ghi 8K | Uhi 8K = 32KB
// ============================================================================
__global__ void __launch_bounds__(512, 2) gu_kernel(int zbase) {
    extern __shared__ __align__(1024) char sm[];
    const int z = blockIdx.z + zbase;
    const int count = (z < E_NUM) ? g_count[z] : T_TOK;
    const int m0 = blockIdx.y * 128;
    if (m0 >= count) return;
    const int n0 = blockIdx.x * 64;

    const int tid = threadIdx.x, lane = tid & 31, wid = tid >> 5;
    const int wm = wid & 3, wn = wid >> 2;
    const uint32_t sb = smem_u32(sm);

    // ---- loader: A — 128 rows, 4 thr/row, 2 units each ----
    const int lr = tid >> 2, lj = (tid & 3) * 2;
    const int mrow = m0 + lr;
    int tok = (z < E_NUM) ? ((mrow < count) ? g_tok[z * T_TOK + mrow] : 0) : mrow;
    const char* srcA = (const char*)(cx + (size_t)tok * H_DIM);
    const uint32_t SA = (uint32_t)(lr & 7) << 4;
    const uint32_t rowA = (uint32_t)(lr * 128);
    uint32_t dA[2];
#pragma unroll
    for (int uu = 0; uu < 2; uu++)
        dA[uu] = rowA + ((((uint32_t)(lj + uu)) << 4) ^ SA);

    // ---- loader: B — 2 buffers (G, U), 64 rows, 4 thr/row, 2 units ----
    const int selB = tid >> 8, rowb = (tid & 255) >> 2, bj = (tid & 3) * 2;
    const __half* wbh;
    if (z < E_NUM) {
        size_t eo = (size_t)z * I_DIM * H_DIM;
        wbh = selB ? cuw + eo : cgw + eo;
    } else {
        wbh = selB ? csu : csg;
    }
    const char* srcB = (const char*)(wbh + (size_t)(n0 + rowb) * H_DIM);
    const uint32_t SB = (uint32_t)(rowb & 7) << 4;
    const uint32_t rowBoff = 16384u + (uint32_t)selB * 8192u + (uint32_t)(rowb * 128);

    auto load_stage = [&](int chunk, int stg) {
        uint32_t base = sb + stg * STG_B;
        int koff = chunk * 128;   // 64 fp16 * 2B
#pragma unroll
        for (int uu = 0; uu < 2; uu++)
            cpa(base + dA[uu], srcA + koff + (lj + uu) * 16);
#pragma unroll
        for (int uu = 0; uu < 2; uu++) {
            uint32_t u = (uint32_t)(bj + uu);
            cpa(base + rowBoff + ((u << 4) ^ SB), srcB + koff + u * 16);
        }
    };

    const int ra = wm * 32 + (((lane >> 3) & 1) << 3) + (lane & 7);
    const uint32_t Sa = (uint32_t)(ra & 7) << 4;
    const int rbn = wn * 16 + (((lane >> 3) & 1) << 3) + (lane & 7);
    const uint32_t Sbn = (uint32_t)(rbn & 7) << 4;
    const uint32_t g2 = (uint32_t)(lane >> 4) << 4;

    float acc[2][2][2][4];   // [mat][mf][nf][4]
#pragma unroll
    for (int a = 0; a < 2; a++)
#pragma unroll
        for (int b = 0; b < 2; b++)
#pragma unroll
            for (int c = 0; c < 2; c++)
#pragma unroll
                for (int d = 0; d < 4; d++) acc[a][b][c][d] = 0.0f;

    load_stage(0, 0); CPA_COMMIT();
    load_stage(1, 1); CPA_COMMIT();

    const int NC = H_DIM / 64;  // 32
    for (int c = 0; c < NC; c++) {
        CPA_WAIT1();
        __syncthreads();
        if (c + 2 < NC) load_stage(c + 2, (c + 2) % NSTG);
        CPA_COMMIT();
        uint32_t base = sb + (c % NSTG) * STG_B;
#pragma unroll
        for (int ks = 0; ks < 4; ks++) {
            uint32_t kx = ((uint32_t)ks << 5) | g2;
            uint32_t Ah[2][4];
#pragma unroll
            for (int mf = 0; mf < 2; mf++) {
                uint32_t ro = (uint32_t)((ra + mf * 16) * 128);
                ldmx4(Ah[mf], base + ro + (kx ^ Sa));
            }
#pragma unroll
            for (int mat = 0; mat < 2; mat++) {
                uint32_t bh[4];
                uint32_t bo = base + 16384u + (uint32_t)mat * 8192u + (uint32_t)(rbn * 128);
                ldmx4(bh, bo + (kx ^ Sbn));
#pragma unroll
                for (int mf = 0; mf < 2; mf++) {
#pragma unroll
                    for (int nf = 0; nf < 2; nf++)
                        mma16816(acc[mat][mf][nf], Ah[mf], bh[nf], bh[nf + 2]);
                }
            }
        }
    }

    // ---- epilogue: silu(g)*u -> h (fp16) ----
    const size_t rowbase = (z < E_NUM) ? (size_t)z * T_TOK : (size_t)E_NUM * T_TOK;
#pragma unroll
    for (int mf = 0; mf < 2; mf++) {
        int R0 = m0 + wm * 32 + mf * 16 + (lane >> 2);
#pragma unroll
        for (int nf = 0; nf < 2; nf++) {
            int C = n0 + wn * 16 + nf * 8 + (lane & 3) * 2;
            float* gf = acc[0][mf][nf];
            float* uf = acc[1][mf][nf];
#pragma unroll
            for (int hr = 0; hr < 2; hr++) {
                int R = R0 + hr * 8;
                if (R < count) {
                    float ga = gf[hr * 2], gb = gf[hr * 2 + 1];
                    float ua = uf[hr * 2], ub = uf[hr * 2 + 1];
                    float ha = ga / (1.0f + __expf(-ga)) * ua;
                    float hb = gb / (1.0f + __expf(-gb)) * ub;
                    *(__half2*)(h_buf + (rowbase + R) * (size_t)I_DIM + C) =
                        __floats2half2_rn(ha, hb);
                }
            }
        }
    }
}

// ============================================================================
// down GEMM: BM=128, BN=128, BK=64, 512 thr = 16 warps (4m x 4n), warp 32x32
// smem/stage: A 16K | B 16K = 32KB
// ============================================================================
__global__ void __launch_bounds__(512, 2) dn_kernel(float* __restrict__ out) {
    extern __shared__ __align__(1024) char sm[];
    const int z = blockIdx.z;
    const int count = (z < E_NUM) ? g_count[z] : T_TOK;
    const int m0 = blockIdx.y * 128;
    if (m0 >= count) return;
    const int n0 = blockIdx.x * 128;

    const int tid = threadIdx.x, lane = tid & 31, wid = tid >> 5;
    const int wm = wid & 3, wn = wid >> 2;
    const uint32_t sb = smem_u32(sm);
    const size_t rowbase = (z < E_NUM) ? (size_t)z * T_TOK : (size_t)E_NUM * T_TOK;

    // ---- loader: A (h rows): 128 rows, 4 thr/row, 2 units ----
    const int lr = tid >> 2, lj = (tid & 3) * 2;
    const char* srcA = (const char*)(h_buf + (rowbase + m0 + lr) * (size_t)I_DIM);
    const uint32_t SA = (uint32_t)(lr & 7) << 4;
    const uint32_t rowA = (uint32_t)(lr * 128);
    uint32_t dA[2];
#pragma unroll
    for (int uu = 0; uu < 2; uu++)
        dA[uu] = rowA + ((((uint32_t)(lj + uu)) << 4) ^ SA);

    // ---- loader: B (down weights): 128 rows, 4 thr/row, 2 units ----
    const __half* wdh = (z < E_NUM) ? cdw + (size_t)z * H_DIM * I_DIM : csd;
    const char* srcB = (const char*)(wdh + (size_t)(n0 + lr) * I_DIM);
    const uint32_t rowBoff = 16384u + rowA;

    auto load_stage = [&](int chunk, int stg) {
        uint32_t base = sb + stg * STG_B;
        int koff = chunk * 128;
#pragma unroll
        for (int uu = 0; uu < 2; uu++) {
            int so = koff + (lj + uu) * 16;
            cpa(base + dA[uu],           srcA + so);
            cpa(base + rowBoff + (dA[uu] - rowA), srcB + so);
        }
    };

    const int ra = wm * 32 + (((lane >> 3) & 1) << 3) + (lane & 7);
    const uint32_t Sa = (uint32_t)(ra & 7) << 4;
    const int rb0 = wn * 32 + (((lane >> 3) & 1) << 3) + (lane & 7);
    const int rb1 = rb0 + 16;
    const uint32_t Sb0 = (uint32_t)(rb0 & 7) << 4;
    const uint32_t Sb1 = (uint32_t)(rb1 & 7) << 4;
    const uint32_t g2 = (uint32_t)(lane >> 4) << 4;

    float acc[2][4][4];   // [mf][nb*2+nf][4]
#pragma unroll
    for (int a = 0; a < 2; a++)
#pragma unroll
        for (int b = 0; b < 4; b++)
#pragma unroll
            for (int c = 0; c < 4; c++) acc[a][b][c] = 0.0f;

    load_stage(0, 0); CPA_COMMIT();
    load_stage(1, 1); CPA_COMMIT();

    const int NC = I_DIM / 64;  // 22
    for (int c = 0; c < NC; c++) {
        CPA_WAIT1();
        __syncthreads();
        if (c + 2 < NC) load_stage(c + 2, (c + 2) % NSTG);
        CPA_COMMIT();
        uint32_t base = sb + (c % NSTG) * STG_B;
#pragma unroll
        for (int ks = 0; ks < 4; ks++) {
            uint32_t kx = ((uint32_t)ks << 5) | g2;
            uint32_t Ah[2][4];
#pragma unroll
            for (int mf = 0; mf < 2; mf++) {
                uint32_t ro = (uint32_t)((ra + mf * 16) * 128);
                ldmx4(Ah[mf], base + ro + (kx ^ Sa));
            }
#pragma unroll
            for (int nb = 0; nb < 2; nb++) {
                uint32_t bh[4];
                uint32_t ro = (uint32_t)((nb ? rb1 : rb0) * 128);
                uint32_t Sx = nb ? Sb1 : Sb0;
                ldmx4(bh, base + 16384u + ro + (kx ^ Sx));
#pragma unroll
                for (int mf = 0; mf < 2; mf++) {
#pragma unroll
                    for (int nf = 0; nf < 2; nf++)
                        mma16816(acc[mf][nb * 2 + nf], Ah[mf], bh[nf], bh[nf + 2]);
                }
            }
        }
    }

    // ---- epilogue: weighted atomic scatter ----
#pragma unroll
    for (int mf = 0; mf < 2; mf++) {
        int R0 = m0 + wm * 32 + mf * 16 + (lane >> 2);
#pragma unroll
        for (int hr = 0; hr < 2; hr++) {
            int R = R0 + hr * 8;
            if (R < count) {
                int t; float wt;
                if (z < E_NUM) { t = g_tok[z * T_TOK + R]; wt = g_wt[z * T_TOK + R]; }
                else           { t = R; wt = 1.0f; }
                float* orow = out + (size_t)t * H_DIM;
#pragma unroll
                for (int q = 0; q < 4; q++) {
                    int C = n0 + wn * 32 + q * 8 + (lane & 3) * 2;
                    atomicAdd(&orow[C],     wt * acc[mf][q][hr * 2]);
                    atomicAdd(&orow[C + 1], wt * acc[mf][q][hr * 2 + 1]);
                }
            }
        }
    }
}

// ---------------- launch ----------------
extern "C" void kernel_launch(void* const* d_in, const int* in_sizes, int n_in,
                              void* d_out, int out_size) {
    const float* x   = (const float*)d_in[0];
    const float* gw  = (const float*)d_in[1];
    const float* egw = (const float*)d_in[2];
    const float* euw = (const float*)d_in[3];
    const float* edw = (const float*)d_in[4];
    const float* sgw = (const float*)d_in[5];
    const float* suw = (const float*)d_in[6];
    const float* sdw = (const float*)d_in[7];
    float* out = (float*)d_out;

    cudaFuncSetAttribute(gu_kernel, cudaFuncAttributeMaxDynamicSharedMemorySize, SMEM_TOT);
    cudaFuncSetAttribute(dn_kernel, cudaFuncAttributeMaxDynamicSharedMemorySize, SMEM_TOT);

    __half *p_cx, *p_cgw, *p_cuw, *p_cdw, *p_csg, *p_csu, *p_csd;
    cudaGetSymbolAddress((void**)&p_cx, cx);
    cudaGetSymbolAddress((void**)&p_cgw, cgw);
    cudaGetSymbolAddress((void**)&p_cuw, cuw);
    cudaGetSymbolAddress((void**)&p_cdw, cdw);
    cudaGetSymbolAddress((void**)&p_csg, csg);
    cudaGetSymbolAddress((void**)&p_csu, csu);
    cudaGetSymbolAddress((void**)&p_csd, csd);

    int n_out = T_TOK * H_DIM;
    zero_kernel<<<(n_out + 255) / 256, 256>>>(out, n_out);                      // 1
    routing_kernel<<<T_TOK / 256, 256>>>(x, gw);                                // 2
    cvt_hi_kernel<<<(X_N / 4 + 255) / 256, 256>>>(x, p_cx, X_N / 4);            // 3
    cvt_hi_kernel<<<(EGW_N / 4 + 255) / 256, 256>>>(egw, p_cgw, EGW_N / 4);     // 4
    cvt_hi_kernel<<<(EGW_N / 4 + 255) / 256, 256>>>(euw, p_cuw, EGW_N / 4);     // 5
    gu_kernel<<<dim3(I_DIM / 64, T_TOK / 128, E_NUM), 512, SMEM_TOT>>>(0);      // 6 <- profiled
    cvt_hi_kernel<<<(EGW_N / 4 + 255) / 256, 256>>>(edw, p_cdw, EGW_N / 4);     // 7
    cvt_hi_kernel<<<(SGW_N / 4 + 255) / 256, 256>>>(sgw, p_csg, SGW_N / 4);     // 8
    cvt_hi_kernel<<<(SGW_N / 4 + 255) / 256, 256>>>(suw, p_csu, SGW_N / 4);     // 9
    cvt_hi_kernel<<<(SGW_N / 4 + 255) / 256, 256>>>(sdw, p_csd, SGW_N / 4);     // 10
    gu_kernel<<<dim3(I_DIM / 64, T_TOK / 128, 1), 512, SMEM_TOT>>>(E_NUM);      // 11 (shared)
    dn_kernel<<<dim3(H_DIM / 128, T_TOK / 128, E_NUM + 1), 512, SMEM_TOT>>>(out); // 12
}